// round 2
// baseline (speedup 1.0000x reference)
#include <cuda_runtime.h>
#include <math.h>

#define NB 128
#define NT 32
#define NIN 512
#define NH 512
#define NM 16
#define NWC 20
#define NR 4
#define NRW 80
#define NNIN 592
#define NIF 163
#define CLIPV 20.0f
#define EPSF 1e-6f
#define DELTAF 5e-6f

// ---------------- persistent state (device globals; allocation-free) ----------
__device__ float g_h[2][2][2][NB][NH];   // [parity][layer][cell][b][h]
__device__ float g_c[2][2][NB][NH];      // [layer][cell][b][h]
__device__ float g_inp[NB][NNIN];        // concat(out, read_vecs)
__device__ float g_mem[2][NB][NM][NWC];
__device__ float g_link[2][NB][NM][NM];
__device__ float g_prec[2][NB][NM];
__device__ float g_rw[2][NB][NR][NM];
__device__ float g_ww[2][NB][NM];
__device__ float g_usage[2][NB][NM];

__device__ __forceinline__ float sigf(float x) { return 1.f / (1.f + expf(-x)); }
__device__ __forceinline__ float softplusf(float x) {
    return fmaxf(x, 0.f) + log1pf(expf(-fabsf(x)));
}
__device__ __forceinline__ float clipf(float x) {
    return fminf(fmaxf(x, -CLIPV), CLIPV);
}

// ---------------- init: zero all state --------------------------------------
__global__ void initk() {
    long i0 = blockIdx.x * (long)blockDim.x + threadIdx.x;
    long st = (long)gridDim.x * blockDim.x;
    for (long i = i0; i < 2L * 2 * 2 * NB * NH; i += st) ((float*)g_h)[i] = 0.f;
    for (long i = i0; i < 2L * 2 * NB * NH; i += st) ((float*)g_c)[i] = 0.f;
    for (long i = i0; i < (long)NB * NNIN; i += st) ((float*)g_inp)[i] = 0.f;
    for (long i = i0; i < 2L * NB * NM * NWC; i += st) ((float*)g_mem)[i] = 0.f;
    for (long i = i0; i < 2L * NB * NM * NM; i += st) ((float*)g_link)[i] = 0.f;
    for (long i = i0; i < 2L * NB * NM; i += st) {
        ((float*)g_prec)[i] = 0.f;
        ((float*)g_ww)[i] = 0.f;
        ((float*)g_usage)[i] = 0.f;
    }
    for (long i = i0; i < 2L * NB * NR * NM; i += st) ((float*)g_rw)[i] = 0.f;
}

// ---------------- fused 4-gate GEMM (+ optional LSTM epilogue) ---------------
// C[b, g*G + jb*16 + jl] = [A1 | A2] @ [W1 | W2]^T (+ biases)
// MODE 0: LSTM cell epilogue (c update, h out, optional clipped copy)
// MODE 1: plain linear (write acc + b1)
// Tile: TM (batch) x 16 (j) x 4 gates, 256 threads, MPT = TM/16 m-rows/thread.
template <int TM, int MODE>
__global__ __launch_bounds__(256) void gemm4k(
    const float* __restrict__ A1, int sA1, int K1,
    const float* __restrict__ A2, int sA2, int K2,
    const float* __restrict__ W1, int ldW1,
    const float* __restrict__ W2, int ldW2,
    const float* __restrict__ b1, const float* __restrict__ b2,
    int G,
    float* __restrict__ cio,
    float* __restrict__ outp, int sOut,
    float* __restrict__ clipOut, int sClip)
{
    __shared__ float As[16 * TM];
    __shared__ float Bs[16 * 64];
    constexpr int MPT = TM / 16;

    const int tid = threadIdx.x;
    const int jl = tid & 15;
    const int mg = tid >> 4;
    const int jb = blockIdx.x;
    const int mb = blockIdx.y;
    const int nch = (K1 + K2) >> 4;

    float acc[MPT][4];
#pragma unroll
    for (int i = 0; i < MPT; ++i)
#pragma unroll
        for (int g = 0; g < 4; ++g) acc[i][g] = 0.f;

    // W-load mapping: 256 float4 slots cover 64 rows x 16 k
    const int lrow = tid >> 2, lkq = tid & 3;
    const int lgg = lrow >> 4, ljj = lrow & 15;
    const int grow = lgg * G + jb * 16 + ljj;
    // A-load mapping: TM*4 float4 slots cover TM rows x 16 k
    const int am = tid >> 2, akq = tid & 3;

    for (int ch = 0; ch < nch; ++ch) {
        const int k0 = ch << 4;
        // issue global loads first
        float4 w;
        {
            const float* Wb; int ldw, kof;
            if (k0 < K1) { Wb = W1; ldw = ldW1; kof = k0; }
            else         { Wb = W2; ldw = ldW2; kof = k0 - K1; }
            w = *(const float4*)(Wb + (size_t)grow * ldw + kof + lkq * 4);
        }
        float4 a = make_float4(0.f, 0.f, 0.f, 0.f);
        if (tid < TM * 4) {
            const float* Ab; int sa, kof;
            if (k0 < K1) { Ab = A1; sa = sA1; kof = k0; }
            else         { Ab = A2; sa = sA2; kof = k0 - K1; }
            a = *(const float4*)(Ab + (size_t)(mb * TM + am) * sa + kof + akq * 4);
        }
        __syncthreads();  // previous tile fully consumed
        Bs[(lkq * 4 + 0) * 64 + ljj * 4 + lgg] = w.x;
        Bs[(lkq * 4 + 1) * 64 + ljj * 4 + lgg] = w.y;
        Bs[(lkq * 4 + 2) * 64 + ljj * 4 + lgg] = w.z;
        Bs[(lkq * 4 + 3) * 64 + ljj * 4 + lgg] = w.w;
        if (tid < TM * 4) {
            As[(akq * 4 + 0) * TM + am] = a.x;
            As[(akq * 4 + 1) * TM + am] = a.y;
            As[(akq * 4 + 2) * TM + am] = a.z;
            As[(akq * 4 + 3) * TM + am] = a.w;
        }
        __syncthreads();
#pragma unroll
        for (int kk = 0; kk < 16; ++kk) {
            float4 bv = *(const float4*)(Bs + kk * 64 + jl * 4);
#pragma unroll
            for (int i = 0; i < MPT; ++i) {
                float av = As[kk * TM + mg * MPT + i];
                acc[i][0] = fmaf(av, bv.x, acc[i][0]);
                acc[i][1] = fmaf(av, bv.y, acc[i][1]);
                acc[i][2] = fmaf(av, bv.z, acc[i][2]);
                acc[i][3] = fmaf(av, bv.w, acc[i][3]);
            }
        }
    }

    const int jc = jb * 16 + jl;
#pragma unroll
    for (int i = 0; i < MPT; ++i) {
        const int b = mb * TM + mg * MPT + i;
        if (MODE == 0) {
            float gi = acc[i][0] + b1[0 * G + jc] + b2[0 * G + jc];
            float gf = acc[i][1] + b1[1 * G + jc] + b2[1 * G + jc];
            float gg = acc[i][2] + b1[2 * G + jc] + b2[2 * G + jc];
            float go = acc[i][3] + b1[3 * G + jc] + b2[3 * G + jc];
            float cold = cio[(size_t)b * NH + jc];
            float cn = sigf(gf) * cold + sigf(gi) * tanhf(gg);
            float hn = sigf(go) * tanhf(cn);
            cio[(size_t)b * NH + jc] = cn;
            outp[(size_t)b * sOut + jc] = hn;
            if (clipOut) clipOut[(size_t)b * sClip + jc] = clipf(hn);
        } else {
#pragma unroll
            for (int g = 0; g < 4; ++g) {
                int col = g * G + jc;
                outp[(size_t)b * sOut + col] = acc[i][g] + b1[col];
            }
        }
    }
}

// ---------------- DNC memory step: iface GEMV + full memory update -----------
// one block per batch row, 128 threads
__global__ __launch_bounds__(128) void memstep(
    const float* __restrict__ hsrc,   // unclipped h1 [NB][NH]
    const float* __restrict__ Wi,     // [NIF][NH]
    const float* __restrict__ bi,     // [NIF]
    float* __restrict__ memg, float* __restrict__ linkg,
    float* __restrict__ precg, float* __restrict__ rwg,
    float* __restrict__ wwg, float* __restrict__ usg,
    float* __restrict__ inp)          // g_inp: read_vecs -> [b][512..591]
{
    // iface layout offsets
    const int RK = 0, RS = 80, WK = 84, WS = 104, ER = 105, WV = 125,
              FG = 145, AG = 149, WG = 150, RM = 151;
    const int b = blockIdx.x;
    const int tid = threadIdx.x;

    __shared__ float xs[NH];
    __shared__ float ifc[NIF];
    __shared__ float sm[NM * NWC];
    __shared__ float sl[NM * NM];
    __shared__ float sp[NM], srw[NR * NM], sww[NM], sus[NM];
    __shared__ float wcw[NM], alo[NM];
    __shared__ float rcw[NR * NM], fwd[NR * NM], bwd[NR * NM];

    for (int i = tid; i < NH; i += 128) xs[i] = clipf(hsrc[(size_t)b * NH + i]);
    for (int i = tid; i < NM * NWC; i += 128) sm[i] = memg[b * NM * NWC + i];
    for (int i = tid; i < NM * NM; i += 128) sl[i] = linkg[b * NM * NM + i];
    if (tid < NM) {
        sp[tid] = precg[b * NM + tid];
        sww[tid] = wwg[b * NM + tid];
        sus[tid] = usg[b * NM + tid];
    }
    if (tid < NR * NM) srw[tid] = rwg[b * NR * NM + tid];
    __syncthreads();

    // iface = Wi @ xs + bi (warp-per-row)
    const int warp = tid >> 5, lane = tid & 31;
    for (int r = warp; r < NIF; r += 4) {
        const float* wr = Wi + (size_t)r * NH;
        float s = 0.f;
        for (int k = lane; k < NH; k += 32) s = fmaf(wr[k], xs[k], s);
#pragma unroll
        for (int o = 16; o > 0; o >>= 1) s += __shfl_down_sync(0xffffffffu, s, o);
        if (lane == 0) ifc[r] = s + bi[r];
    }
    __syncthreads();

    // usage update (uses OLD ww, OLD rw)
    if (tid < NM) {
        int m = tid;
        float uu = sus[m] + (1.f - sus[m]) * sww[m];
        float psi = 1.f;
#pragma unroll
        for (int r = 0; r < NR; ++r)
            psi *= 1.f - sigf(ifc[FG + r]) * srw[r * NM + m];
        sus[m] = uu * psi;
    }
    __syncthreads();

    // write content weights (cosine on OLD memory)
    if (tid < NM) {
        int m = tid;
        float kn2 = 0.f, dot = 0.f, mn2 = 0.f;
#pragma unroll
        for (int w = 0; w < NWC; ++w) {
            float kv = tanhf(ifc[WK + w]);
            float mv = sm[m * NWC + w];
            kn2 = fmaf(kv, kv, kn2);
            mn2 = fmaf(mv, mv, mn2);
            dot = fmaf(kv, mv, dot);
        }
        wcw[m] = dot / ((sqrtf(kn2) + EPSF) * (sqrtf(mn2) + EPSF));
    }
    __syncthreads();
    if (tid == 0) {
        float str = softplusf(ifc[WS]);
        float mx = -1e30f;
        for (int m = 0; m < NM; ++m) { wcw[m] *= str; mx = fmaxf(mx, wcw[m]); }
        float s = 0.f;
        for (int m = 0; m < NM; ++m) { wcw[m] = expf(wcw[m] - mx); s += wcw[m]; }
        float inv = 1.f / s;
        for (int m = 0; m < NM; ++m) wcw[m] *= inv;
    }
    // allocation weights (stable ascending argsort of u)
    if (tid == 32) {
        float u[NM]; int idx[NM];
        for (int m = 0; m < NM; ++m) { u[m] = DELTAF + (1.f - DELTAF) * sus[m]; idx[m] = m; }
        for (int i = 1; i < NM; ++i) {
            float kv = u[i]; int ki = idx[i]; int j = i;
            while (j > 0 && u[j - 1] > kv) { u[j] = u[j - 1]; idx[j] = idx[j - 1]; --j; }
            u[j] = kv; idx[j] = ki;
        }
        float prod = 1.f;
        for (int j = 0; j < NM; ++j) { alo[idx[j]] = (1.f - u[j]) * prod; prod *= u[j]; }
    }
    __syncthreads();

    // new write weights
    if (tid < NM) {
        float ag = sigf(ifc[AG]), wg = sigf(ifc[WG]);
        sww[tid] = wg * (ag * alo[tid] + (1.f - ag) * wcw[tid]);
    }
    __syncthreads();

    // memory write
    for (int i = tid; i < NM * NWC; i += 128) {
        int m = i / NWC, w = i % NWC;
        float e = sigf(ifc[ER + w]);
        float v = tanhf(ifc[WV + w]);
        sm[i] = sm[i] * (1.f - sww[m] * e) + sww[m] * v;
    }
    __syncthreads();

    // link update (uses NEW ww, OLD prec)
    for (int i = tid; i < NM * NM; i += 128) {
        int ii = i >> 4, jj = i & 15;
        sl[i] = (ii == jj) ? 0.f
                           : (1.f - sww[ii] - sww[jj]) * sl[i] + sww[ii] * sp[jj];
    }
    __syncthreads();

    // precedence
    if (tid < NM) {
        float s = 0.f;
#pragma unroll
        for (int m = 0; m < NM; ++m) s += sww[m];
        sp[tid] = (1.f - s) * sp[tid] + sww[tid];
    }
    __syncthreads();

    // read content weights (cosine on NEW memory)
    if (tid < NR * NM) {
        int r = tid >> 4, m = tid & 15;
        float kn2 = 0.f, dot = 0.f, mn2 = 0.f;
#pragma unroll
        for (int w = 0; w < NWC; ++w) {
            float kv = tanhf(ifc[RK + r * NWC + w]);
            float mv = sm[m * NWC + w];
            kn2 = fmaf(kv, kv, kn2);
            mn2 = fmaf(mv, mv, mn2);
            dot = fmaf(kv, mv, dot);
        }
        rcw[tid] = dot / ((sqrtf(kn2) + EPSF) * (sqrtf(mn2) + EPSF));
    }
    __syncthreads();
    if (tid < NR) {
        int r = tid;
        float str = softplusf(ifc[RS + r]);
        float mx = -1e30f;
        for (int m = 0; m < NM; ++m) { rcw[r * NM + m] *= str; mx = fmaxf(mx, rcw[r * NM + m]); }
        float s = 0.f;
        for (int m = 0; m < NM; ++m) { rcw[r * NM + m] = expf(rcw[r * NM + m] - mx); s += rcw[r * NM + m]; }
        float inv = 1.f / s;
        for (int m = 0; m < NM; ++m) rcw[r * NM + m] *= inv;
    }
    __syncthreads();

    // forward / backward weights (NEW link, OLD rw)
    if (tid < NR * NM) {
        int r = tid >> 4, q = tid & 15;
        float f = 0.f, bb = 0.f;
#pragma unroll
        for (int j = 0; j < NM; ++j) {
            f = fmaf(sl[q * NM + j], srw[r * NM + j], f);
            bb = fmaf(srw[r * NM + j], sl[j * NM + q], bb);
        }
        fwd[tid] = f;
        bwd[tid] = bb;
    }
    __syncthreads();

    // new read weights (mode softmax over 3)
    if (tid < NR * NM) {
        int r = tid >> 4;
        float e0 = ifc[RM + r * 3 + 0], e1 = ifc[RM + r * 3 + 1], e2 = ifc[RM + r * 3 + 2];
        float mx = fmaxf(e0, fmaxf(e1, e2));
        float x0 = expf(e0 - mx), x1 = expf(e1 - mx), x2 = expf(e2 - mx);
        float inv = 1.f / (x0 + x1 + x2);
        srw[tid] = (x0 * bwd[tid] + x1 * fwd[tid] + x2 * rcw[tid]) * inv;
    }
    __syncthreads();

    // read vectors -> g_inp[:, 512:592]
    if (tid < NRW) {
        int r = tid / NWC, w = tid % NWC;
        float s = 0.f;
#pragma unroll
        for (int m = 0; m < NM; ++m) s = fmaf(srw[r * NM + m], sm[m * NWC + w], s);
        inp[(size_t)b * NNIN + NIN + tid] = s;
    }

    // write back state
    for (int i = tid; i < NM * NWC; i += 128) memg[b * NM * NWC + i] = sm[i];
    for (int i = tid; i < NM * NM; i += 128) linkg[b * NM * NM + i] = sl[i];
    if (tid < NM) {
        precg[b * NM + tid] = sp[tid];
        wwg[b * NM + tid] = sww[tid];
        usg[b * NM + tid] = sus[tid];
    }
    if (tid < NR * NM) rwg[b * NR * NM + tid] = srw[tid];
}

// ---------------- host driver ------------------------------------------------
extern "C" void kernel_launch(void* const* d_in, const int* in_sizes, int n_in,
                              void* d_out, int out_size)
{
    const float* x      = (const float*)d_in[0];
    const float* W_ih0  = (const float*)d_in[1];
    const float* W_hh0  = (const float*)d_in[2];
    const float* b_ih0  = (const float*)d_in[3];
    const float* b_hh0  = (const float*)d_in[4];
    const float* W_ih1  = (const float*)d_in[5];
    const float* W_hh1  = (const float*)d_in[6];
    const float* b_ih1  = (const float*)d_in[7];
    const float* b_hh1  = (const float*)d_in[8];
    const float* W_if   = (const float*)d_in[9];
    const float* b_if   = (const float*)d_in[10];
    const float* W_out  = (const float*)d_in[11];
    const float* b_out  = (const float*)d_in[12];
    float* y = (float*)d_out;

    float *ph, *pc, *pinp, *pmem, *plink, *pprec, *prw, *pww, *pus;
    cudaGetSymbolAddress((void**)&ph,   g_h);
    cudaGetSymbolAddress((void**)&pc,   g_c);
    cudaGetSymbolAddress((void**)&pinp, g_inp);
    cudaGetSymbolAddress((void**)&pmem, g_mem);
    cudaGetSymbolAddress((void**)&plink,g_link);
    cudaGetSymbolAddress((void**)&pprec,g_prec);
    cudaGetSymbolAddress((void**)&prw,  g_rw);
    cudaGetSymbolAddress((void**)&pww,  g_ww);
    cudaGetSymbolAddress((void**)&pus,  g_usage);

    auto hbuf = [&](int p, int l, int s) {
        return ph + (((size_t)p * 2 + l) * 2 + s) * NB * NH;
    };
    auto cbuf = [&](int l, int s) { return pc + ((size_t)l * 2 + s) * NB * NH; };

    initk<<<512, 256>>>();

    const dim3 gL(NH / 16, NB / 32);     // LSTM cells
    const dim3 gO(128 / 16, NB / 16);    // output projection (G=128)

    for (int t = 0; t < NT; ++t) {
        const int p = t & 1;
        for (int l = 0; l < 2; ++l) {
            // ---- cell 0 ----
            const float* A1; int sA1, K1; const float* Wih;
            if (l == 0) { A1 = x + (size_t)t * NIN; sA1 = NT * NIN; K1 = NIN; Wih = W_ih0; }
            else        { A1 = pinp; sA1 = NNIN; K1 = NNIN; Wih = W_ih0 + (size_t)4 * NH * NNIN; }
            gemm4k<32, 0><<<gL, 256>>>(
                A1, sA1, K1,
                hbuf(p, l, 0), NH, NH,
                Wih, NNIN,
                W_hh0 + (size_t)l * 4 * NH * NH, NH,
                b_ih0 + (size_t)l * 4 * NH, b_hh0 + (size_t)l * 4 * NH,
                NH,
                cbuf(l, 0),
                hbuf(p ^ 1, l, 0), NH,
                nullptr, 0);
            // ---- cell 1 ----
            gemm4k<32, 0><<<gL, 256>>>(
                hbuf(p ^ 1, l, 0), NH, NH,
                hbuf(p, l, 1), NH, NH,
                W_ih1 + (size_t)l * 4 * NH * NH, NH,
                W_hh1 + (size_t)l * 4 * NH * NH, NH,
                b_ih1 + (size_t)l * 4 * NH, b_hh1 + (size_t)l * 4 * NH,
                NH,
                cbuf(l, 1),
                hbuf(p ^ 1, l, 1), NH,
                pinp, NNIN);
            // ---- memory step ----
            memstep<<<NB, 128>>>(
                hbuf(p ^ 1, l, 1),
                W_if + (size_t)l * NIF * NH, b_if + (size_t)l * NIF,
                pmem + (size_t)l * NB * NM * NWC,
                plink + (size_t)l * NB * NM * NM,
                pprec + (size_t)l * NB * NM,
                prw + (size_t)l * NB * NR * NM,
                pww + (size_t)l * NB * NM,
                pus + (size_t)l * NB * NM,
                pinp);
        }
        // ---- output projection: y_t = g_inp @ W_out^T + b_out ----
        gemm4k<16, 1><<<gO, 256>>>(
            pinp, NNIN, NNIN,
            nullptr, 0, 0,
            W_out, NNIN,
            nullptr, 0,
            b_out, nullptr,
            128,
            nullptr,
            y + (size_t)t * NIN, NT * NIN,
            nullptr, 0);
    }
}

// round 3
// speedup vs baseline: 1.2026x; 1.2026x over previous
#include <cuda_runtime.h>
#include <math.h>

#define NB 128
#define NT 32
#define NIN 512
#define NH 512
#define NM 16
#define NWC 20
#define NR 4
#define NRW 80
#define NNIN 592
#define NIF 163
#define CLIPV 20.0f
#define EPSF 1e-6f
#define DELTAF 5e-6f

// ---------------- persistent state (device globals; allocation-free) ----------
__device__ float g_h[2][2][2][NB][NH];   // [parity][layer][cell][b][h]
__device__ float g_c[2][2][NB][NH];      // [layer][cell][b][h]
__device__ float g_inp[NB][NNIN];        // concat(out, read_vecs)
__device__ float g_mem[2][NB][NM][NWC];
__device__ float g_link[2][NB][NM][NM];
__device__ float g_prec[2][NB][NM];
__device__ float g_rw[2][NB][NR][NM];
__device__ float g_ww[2][NB][NM];
__device__ float g_usage[2][NB][NM];

__device__ __forceinline__ float sigf(float x) { return 1.f / (1.f + expf(-x)); }
__device__ __forceinline__ float softplusf(float x) {
    return fmaxf(x, 0.f) + log1pf(expf(-fabsf(x)));
}
__device__ __forceinline__ float clipf(float x) {
    return fminf(fmaxf(x, -CLIPV), CLIPV);
}

// ---------------- init: zero all state --------------------------------------
__global__ void initk() {
    long i0 = blockIdx.x * (long)blockDim.x + threadIdx.x;
    long st = (long)gridDim.x * blockDim.x;
    for (long i = i0; i < 2L * 2 * 2 * NB * NH; i += st) ((float*)g_h)[i] = 0.f;
    for (long i = i0; i < 2L * 2 * NB * NH; i += st) ((float*)g_c)[i] = 0.f;
    for (long i = i0; i < (long)NB * NNIN; i += st) ((float*)g_inp)[i] = 0.f;
    for (long i = i0; i < 2L * NB * NM * NWC; i += st) ((float*)g_mem)[i] = 0.f;
    for (long i = i0; i < 2L * NB * NM * NM; i += st) ((float*)g_link)[i] = 0.f;
    for (long i = i0; i < 2L * NB * NM; i += st) {
        ((float*)g_prec)[i] = 0.f;
        ((float*)g_ww)[i] = 0.f;
        ((float*)g_usage)[i] = 0.f;
    }
    for (long i = i0; i < 2L * NB * NR * NM; i += st) ((float*)g_rw)[i] = 0.f;
}

// ---------------- fused 4-gate GEMM (+ optional LSTM epilogue) ---------------
// C[b, g*G + jb*16 + jl] = [A1 | A2] @ [W1 | W2]^T (+ biases)
// MODE 0: LSTM cell epilogue (c update, h out, optional clipped copy)
// MODE 1: plain linear (write acc + b1)
// Tile: TM (batch) x 16 (j) x 4 gates, 256 threads, MPT = TM/16 m-rows/thread.
template <int TM, int MODE>
__global__ __launch_bounds__(256) void gemm4k(
    const float* __restrict__ A1, int sA1, int K1,
    const float* __restrict__ A2, int sA2, int K2,
    const float* __restrict__ W1, int ldW1,
    const float* __restrict__ W2, int ldW2,
    const float* __restrict__ b1, const float* __restrict__ b2,
    int G,
    float* __restrict__ cio,
    float* __restrict__ outp, int sOut,
    float* __restrict__ clipOut, int sClip)
{
    __shared__ float As[16 * TM];
    __shared__ float Bs[16 * 64];
    constexpr int MPT = TM / 16;

    const int tid = threadIdx.x;
    const int jl = tid & 15;
    const int mg = tid >> 4;
    const int jb = blockIdx.x;
    const int mb = blockIdx.y;
    const int nch = (K1 + K2) >> 4;

    float acc[MPT][4];
#pragma unroll
    for (int i = 0; i < MPT; ++i)
#pragma unroll
        for (int g = 0; g < 4; ++g) acc[i][g] = 0.f;

    // W-load mapping: 256 float4 slots cover 64 rows x 16 k
    const int lrow = tid >> 2, lkq = tid & 3;
    const int lgg = lrow >> 4, ljj = lrow & 15;
    const int grow = lgg * G + jb * 16 + ljj;
    // A-load mapping: TM*4 float4 slots cover TM rows x 16 k
    const int am = tid >> 2, akq = tid & 3;

    for (int ch = 0; ch < nch; ++ch) {
        const int k0 = ch << 4;
        // issue global loads first
        float4 w;
        {
            const float* Wb; int ldw, kof;
            if (k0 < K1) { Wb = W1; ldw = ldW1; kof = k0; }
            else         { Wb = W2; ldw = ldW2; kof = k0 - K1; }
            w = *(const float4*)(Wb + (size_t)grow * ldw + kof + lkq * 4);
        }
        float4 a = make_float4(0.f, 0.f, 0.f, 0.f);
        if (tid < TM * 4) {
            const float* Ab; int sa, kof;
            if (k0 < K1) { Ab = A1; sa = sA1; kof = k0; }
            else         { Ab = A2; sa = sA2; kof = k0 - K1; }
            a = *(const float4*)(Ab + (size_t)(mb * TM + am) * sa + kof + akq * 4);
        }
        __syncthreads();  // previous tile fully consumed
        Bs[(lkq * 4 + 0) * 64 + ljj * 4 + lgg] = w.x;
        Bs[(lkq * 4 + 1) * 64 + ljj * 4 + lgg] = w.y;
        Bs[(lkq * 4 + 2) * 64 + ljj * 4 + lgg] = w.z;
        Bs[(lkq * 4 + 3) * 64 + ljj * 4 + lgg] = w.w;
        if (tid < TM * 4) {
            As[(akq * 4 + 0) * TM + am] = a.x;
            As[(akq * 4 + 1) * TM + am] = a.y;
            As[(akq * 4 + 2) * TM + am] = a.z;
            As[(akq * 4 + 3) * TM + am] = a.w;
        }
        __syncthreads();
#pragma unroll
        for (int kk = 0; kk < 16; ++kk) {
            float4 bv = *(const float4*)(Bs + kk * 64 + jl * 4);
#pragma unroll
            for (int i = 0; i < MPT; ++i) {
                float av = As[kk * TM + mg * MPT + i];
                acc[i][0] = fmaf(av, bv.x, acc[i][0]);
                acc[i][1] = fmaf(av, bv.y, acc[i][1]);
                acc[i][2] = fmaf(av, bv.z, acc[i][2]);
                acc[i][3] = fmaf(av, bv.w, acc[i][3]);
            }
        }
    }

    const int jc = jb * 16 + jl;
#pragma unroll
    for (int i = 0; i < MPT; ++i) {
        const int b = mb * TM + mg * MPT + i;
        if (MODE == 0) {
            float gi = acc[i][0] + b1[0 * G + jc] + b2[0 * G + jc];
            float gf = acc[i][1] + b1[1 * G + jc] + b2[1 * G + jc];
            float gg = acc[i][2] + b1[2 * G + jc] + b2[2 * G + jc];
            float go = acc[i][3] + b1[3 * G + jc] + b2[3 * G + jc];
            float cold = cio[(size_t)b * NH + jc];
            float cn = sigf(gf) * cold + sigf(gi) * tanhf(gg);
            float hn = sigf(go) * tanhf(cn);
            cio[(size_t)b * NH + jc] = cn;
            outp[(size_t)b * sOut + jc] = hn;
            if (clipOut) clipOut[(size_t)b * sClip + jc] = clipf(hn);
        } else {
#pragma unroll
            for (int g = 0; g < 4; ++g) {
                int col = g * G + jc;
                outp[(size_t)b * sOut + col] = acc[i][g] + b1[col];
            }
        }
    }
}

// ---------------- DNC memory step: iface GEMV + full memory update -----------
// one block per batch row, 512 threads (16 warps).
// iface GEMV: warp-per-row, float4 loads, 4 independent accumulator chains
// per lane so the L2 loads overlap (MLP=4) instead of serializing.
__global__ __launch_bounds__(512) void memstep(
    const float* __restrict__ hsrc,   // unclipped h1 [NB][NH]
    const float* __restrict__ Wi,     // [NIF][NH]
    const float* __restrict__ bi,     // [NIF]
    float* __restrict__ memg, float* __restrict__ linkg,
    float* __restrict__ precg, float* __restrict__ rwg,
    float* __restrict__ wwg, float* __restrict__ usg,
    float* __restrict__ inp)          // g_inp: read_vecs -> [b][512..591]
{
    // iface layout offsets
    const int RK = 0, RS = 80, WK = 84, WS = 104, ER = 105, WV = 125,
              FG = 145, AG = 149, WG = 150, RM = 151;
    const int b = blockIdx.x;
    const int tid = threadIdx.x;

    __shared__ __align__(16) float xs[NH];
    __shared__ float ifc[NIF];
    __shared__ float sm[NM * NWC];
    __shared__ float sl[NM * NM];
    __shared__ float sp[NM], srw[NR * NM], sww[NM], sus[NM];
    __shared__ float wcw[NM], alo[NM];
    __shared__ float rcw[NR * NM], fwd[NR * NM], bwd[NR * NM];

    // vectorized load + clip of x (h1)
    if (tid < NH / 4) {
        float4 v = ((const float4*)(hsrc + (size_t)b * NH))[tid];
        v.x = clipf(v.x); v.y = clipf(v.y); v.z = clipf(v.z); v.w = clipf(v.w);
        ((float4*)xs)[tid] = v;
    }
    for (int i = tid; i < NM * NWC; i += 512) sm[i] = memg[b * NM * NWC + i];
    for (int i = tid; i < NM * NM; i += 512) sl[i] = linkg[b * NM * NM + i];
    if (tid < NM) {
        sp[tid] = precg[b * NM + tid];
        sww[tid] = wwg[b * NM + tid];
        sus[tid] = usg[b * NM + tid];
    }
    if (tid >= 32 && tid < 32 + NR * NM) srw[tid - 32] = rwg[b * NR * NM + tid - 32];
    __syncthreads();

    // iface = Wi @ xs + bi : warp-per-row, 16 warps cover 163 rows in 11 passes
    const int warp = tid >> 5, lane = tid & 31;
    const float4* xs4 = (const float4*)xs;
    for (int r = warp; r < NIF; r += 16) {
        const float4* wr = (const float4*)(Wi + (size_t)r * NH);
        float s0 = 0.f, s1 = 0.f, s2 = 0.f, s3 = 0.f;
        float4 w0 = wr[lane];
        float4 w1 = wr[lane + 32];
        float4 w2 = wr[lane + 64];
        float4 w3 = wr[lane + 96];
        float4 x0 = xs4[lane];
        float4 x1 = xs4[lane + 32];
        float4 x2 = xs4[lane + 64];
        float4 x3 = xs4[lane + 96];
        s0 = fmaf(w0.x, x0.x, fmaf(w0.y, x0.y, fmaf(w0.z, x0.z, w0.w * x0.w)));
        s1 = fmaf(w1.x, x1.x, fmaf(w1.y, x1.y, fmaf(w1.z, x1.z, w1.w * x1.w)));
        s2 = fmaf(w2.x, x2.x, fmaf(w2.y, x2.y, fmaf(w2.z, x2.z, w2.w * x2.w)));
        s3 = fmaf(w3.x, x3.x, fmaf(w3.y, x3.y, fmaf(w3.z, x3.z, w3.w * x3.w)));
        float s = (s0 + s1) + (s2 + s3);
#pragma unroll
        for (int o = 16; o > 0; o >>= 1) s += __shfl_down_sync(0xffffffffu, s, o);
        if (lane == 0) ifc[r] = s + bi[r];
    }
    __syncthreads();

    // usage update (uses OLD ww, OLD rw)
    if (tid < NM) {
        int m = tid;
        float uu = sus[m] + (1.f - sus[m]) * sww[m];
        float psi = 1.f;
#pragma unroll
        for (int r = 0; r < NR; ++r)
            psi *= 1.f - sigf(ifc[FG + r]) * srw[r * NM + m];
        sus[m] = uu * psi;
    }
    __syncthreads();

    // write content weights (cosine on OLD memory)
    if (tid < NM) {
        int m = tid;
        float kn2 = 0.f, dot = 0.f, mn2 = 0.f;
#pragma unroll
        for (int w = 0; w < NWC; ++w) {
            float kv = tanhf(ifc[WK + w]);
            float mv = sm[m * NWC + w];
            kn2 = fmaf(kv, kv, kn2);
            mn2 = fmaf(mv, mv, mn2);
            dot = fmaf(kv, mv, dot);
        }
        wcw[m] = dot / ((sqrtf(kn2) + EPSF) * (sqrtf(mn2) + EPSF));
    }
    __syncthreads();
    if (tid == 0) {
        float str = softplusf(ifc[WS]);
        float mx = -1e30f;
        for (int m = 0; m < NM; ++m) { wcw[m] *= str; mx = fmaxf(mx, wcw[m]); }
        float s = 0.f;
        for (int m = 0; m < NM; ++m) { wcw[m] = expf(wcw[m] - mx); s += wcw[m]; }
        float inv = 1.f / s;
        for (int m = 0; m < NM; ++m) wcw[m] *= inv;
    }
    // allocation weights (stable ascending argsort of u)
    if (tid == 32) {
        float u[NM]; int idx[NM];
        for (int m = 0; m < NM; ++m) { u[m] = DELTAF + (1.f - DELTAF) * sus[m]; idx[m] = m; }
        for (int i = 1; i < NM; ++i) {
            float kv = u[i]; int ki = idx[i]; int j = i;
            while (j > 0 && u[j - 1] > kv) { u[j] = u[j - 1]; idx[j] = idx[j - 1]; --j; }
            u[j] = kv; idx[j] = ki;
        }
        float prod = 1.f;
        for (int j = 0; j < NM; ++j) { alo[idx[j]] = (1.f - u[j]) * prod; prod *= u[j]; }
    }
    __syncthreads();

    // new write weights
    if (tid < NM) {
        float ag = sigf(ifc[AG]), wg = sigf(ifc[WG]);
        sww[tid] = wg * (ag * alo[tid] + (1.f - ag) * wcw[tid]);
    }
    __syncthreads();

    // memory write
    if (tid < NM * NWC) {
        int m = tid / NWC, w = tid % NWC;
        float e = sigf(ifc[ER + w]);
        float v = tanhf(ifc[WV + w]);
        sm[tid] = sm[tid] * (1.f - sww[m] * e) + sww[m] * v;
    }
    __syncthreads();

    // link update (uses NEW ww, OLD prec)
    if (tid < NM * NM) {
        int ii = tid >> 4, jj = tid & 15;
        sl[tid] = (ii == jj) ? 0.f
                             : (1.f - sww[ii] - sww[jj]) * sl[tid] + sww[ii] * sp[jj];
    }
    __syncthreads();

    // precedence
    if (tid < NM) {
        float s = 0.f;
#pragma unroll
        for (int m = 0; m < NM; ++m) s += sww[m];
        sp[tid] = (1.f - s) * sp[tid] + sww[tid];
    }
    __syncthreads();

    // read content weights (cosine on NEW memory)
    if (tid < NR * NM) {
        int r = tid >> 4, m = tid & 15;
        float kn2 = 0.f, dot = 0.f, mn2 = 0.f;
#pragma unroll
        for (int w = 0; w < NWC; ++w) {
            float kv = tanhf(ifc[RK + r * NWC + w]);
            float mv = sm[m * NWC + w];
            kn2 = fmaf(kv, kv, kn2);
            mn2 = fmaf(mv, mv, mn2);
            dot = fmaf(kv, mv, dot);
        }
        rcw[tid] = dot / ((sqrtf(kn2) + EPSF) * (sqrtf(mn2) + EPSF));
    }
    __syncthreads();
    if (tid < NR) {
        int r = tid;
        float str = softplusf(ifc[RS + r]);
        float mx = -1e30f;
        for (int m = 0; m < NM; ++m) { rcw[r * NM + m] *= str; mx = fmaxf(mx, rcw[r * NM + m]); }
        float s = 0.f;
        for (int m = 0; m < NM; ++m) { rcw[r * NM + m] = expf(rcw[r * NM + m] - mx); s += rcw[r * NM + m]; }
        float inv = 1.f / s;
        for (int m = 0; m < NM; ++m) rcw[r * NM + m] *= inv;
    }
    __syncthreads();

    // forward / backward weights (NEW link, OLD rw)
    if (tid < NR * NM) {
        int r = tid >> 4, q = tid & 15;
        float f = 0.f, bb = 0.f;
#pragma unroll
        for (int j = 0; j < NM; ++j) {
            f = fmaf(sl[q * NM + j], srw[r * NM + j], f);
            bb = fmaf(srw[r * NM + j], sl[j * NM + q], bb);
        }
        fwd[tid] = f;
        bwd[tid] = bb;
    }
    __syncthreads();

    // new read weights (mode softmax over 3)
    if (tid < NR * NM) {
        int r = tid >> 4;
        float e0 = ifc[RM + r * 3 + 0], e1 = ifc[RM + r * 3 + 1], e2 = ifc[RM + r * 3 + 2];
        float mx = fmaxf(e0, fmaxf(e1, e2));
        float x0 = expf(e0 - mx), x1 = expf(e1 - mx), x2 = expf(e2 - mx);
        float inv = 1.f / (x0 + x1 + x2);
        srw[tid] = (x0 * bwd[tid] + x1 * fwd[tid] + x2 * rcw[tid]) * inv;
    }
    __syncthreads();

    // read vectors -> g_inp[:, 512:592]
    if (tid < NRW) {
        int r = tid / NWC, w = tid % NWC;
        float s = 0.f;
#pragma unroll
        for (int m = 0; m < NM; ++m) s = fmaf(srw[r * NM + m], sm[m * NWC + w], s);
        inp[(size_t)b * NNIN + NIN + tid] = s;
    }

    // write back state
    if (tid < NM * NWC) memg[b * NM * NWC + tid] = sm[tid];
    if (tid >= 256 && tid < 256 + NM * NM) linkg[b * NM * NM + tid - 256] = sl[tid - 256];
    if (tid < NM) {
        precg[b * NM + tid] = sp[tid];
        wwg[b * NM + tid] = sww[tid];
        usg[b * NM + tid] = sus[tid];
    }
    if (tid >= 128 && tid < 128 + NR * NM) rwg[b * NR * NM + tid - 128] = srw[tid - 128];
}

// ---------------- host driver ------------------------------------------------
extern "C" void kernel_launch(void* const* d_in, const int* in_sizes, int n_in,
                              void* d_out, int out_size)
{
    const float* x      = (const float*)d_in[0];
    const float* W_ih0  = (const float*)d_in[1];
    const float* W_hh0  = (const float*)d_in[2];
    const float* b_ih0  = (const float*)d_in[3];
    const float* b_hh0  = (const float*)d_in[4];
    const float* W_ih1  = (const float*)d_in[5];
    const float* W_hh1  = (const float*)d_in[6];
    const float* b_ih1  = (const float*)d_in[7];
    const float* b_hh1  = (const float*)d_in[8];
    const float* W_if   = (const float*)d_in[9];
    const float* b_if   = (const float*)d_in[10];
    const float* W_out  = (const float*)d_in[11];
    const float* b_out  = (const float*)d_in[12];
    float* y = (float*)d_out;

    float *ph, *pc, *pinp, *pmem, *plink, *pprec, *prw, *pww, *pus;
    cudaGetSymbolAddress((void**)&ph,   g_h);
    cudaGetSymbolAddress((void**)&pc,   g_c);
    cudaGetSymbolAddress((void**)&pinp, g_inp);
    cudaGetSymbolAddress((void**)&pmem, g_mem);
    cudaGetSymbolAddress((void**)&plink,g_link);
    cudaGetSymbolAddress((void**)&pprec,g_prec);
    cudaGetSymbolAddress((void**)&prw,  g_rw);
    cudaGetSymbolAddress((void**)&pww,  g_ww);
    cudaGetSymbolAddress((void**)&pus,  g_usage);

    auto hbuf = [&](int p, int l, int s) {
        return ph + (((size_t)p * 2 + l) * 2 + s) * NB * NH;
    };
    auto cbuf = [&](int l, int s) { return pc + ((size_t)l * 2 + s) * NB * NH; };

    initk<<<512, 256>>>();

    const dim3 gL(NH / 16, NB / 32);     // LSTM cells
    const dim3 gO(128 / 16, NB / 16);    // output projection (G=128)

    for (int t = 0; t < NT; ++t) {
        const int p = t & 1;
        for (int l = 0; l < 2; ++l) {
            // ---- cell 0 ----
            const float* A1; int sA1, K1; const float* Wih;
            if (l == 0) { A1 = x + (size_t)t * NIN; sA1 = NT * NIN; K1 = NIN; Wih = W_ih0; }
            else        { A1 = pinp; sA1 = NNIN; K1 = NNIN; Wih = W_ih0 + (size_t)4 * NH * NNIN; }
            gemm4k<32, 0><<<gL, 256>>>(
                A1, sA1, K1,
                hbuf(p, l, 0), NH, NH,
                Wih, NNIN,
                W_hh0 + (size_t)l * 4 * NH * NH, NH,
                b_ih0 + (size_t)l * 4 * NH, b_hh0 + (size_t)l * 4 * NH,
                NH,
                cbuf(l, 0),
                hbuf(p ^ 1, l, 0), NH,
                nullptr, 0);
            // ---- cell 1 ----
            gemm4k<32, 0><<<gL, 256>>>(
                hbuf(p ^ 1, l, 0), NH, NH,
                hbuf(p, l, 1), NH, NH,
                W_ih1 + (size_t)l * 4 * NH * NH, NH,
                W_hh1 + (size_t)l * 4 * NH * NH, NH,
                b_ih1 + (size_t)l * 4 * NH, b_hh1 + (size_t)l * 4 * NH,
                NH,
                cbuf(l, 1),
                hbuf(p ^ 1, l, 1), NH,
                pinp, NNIN);
            // ---- memory step ----
            memstep<<<NB, 512>>>(
                hbuf(p ^ 1, l, 1),
                W_if + (size_t)l * NIF * NH, b_if + (size_t)l * NIF,
                pmem + (size_t)l * NB * NM * NWC,
                plink + (size_t)l * NB * NM * NM,
                pprec + (size_t)l * NB * NM,
                prw + (size_t)l * NB * NR * NM,
                pww + (size_t)l * NB * NM,
                pus + (size_t)l * NB * NM,
                pinp);
        }
        // ---- output projection: y_t = g_inp @ W_out^T + b_out ----
        gemm4k<16, 1><<<gO, 256>>>(
            pinp, NNIN, NNIN,
            nullptr, 0, 0,
            W_out, NNIN,
            nullptr, 0,
            b_out, nullptr,
            128,
            nullptr,
            y + (size_t)t * NIN, NT * NIN,
            nullptr, 0);
    }
}